// round 16
// baseline (speedup 1.0000x reference)
#include <cuda_runtime.h>
#include <cuda_fp16.h>
#include <math.h>
#include <stdint.h>

// PatchEmbedding via single-pass fp16 mma.sync GEMM (sm_103 non-'a': no tcgen05).
// D = GELU( A @ W + b ), M=12544, K=768, N=768, fp32 in/out, fp32 accumulate.
//
// R15 architecture, but 4 warps/CTA with 64x64 warp tiles (2M x 2N):
// LDSM bytes/MMA drop 192 -> 128 (B fragments re-read 2x instead of 4x),
// taking the smem crossbar (previously co-limiting with tensor) off the
// critical path. CTA 128x128, BK=64, 3-stage cp.async, occupancy 2.

#define M_TOTAL 12544
#define K_TOTAL 768
#define N_TOTAL 768
#define BM      128
#define BN      128
#define BK      64              // fp16 per k-tile row chunk (128 B rows)
#define KTILES  12              // 768 / 64
#define TILE_B  16384           // 128 rows * 128 B
#define STAGE_B (2 * TILE_B)    // A tile + B tile
#define NSTAGE  3
#define SMEM_DYN (NSTAGE * STAGE_B + 1024)
#define NTH     128

// ---------------- device scratch ----------------
__device__ __half g_A16[(size_t)M_TOTAL * K_TOTAL];
__device__ __half g_B16[(size_t)N_TOTAL * K_TOTAL];   // W transposed: [N,K]

__device__ __forceinline__ float gelu_exact(float x) {
    return 0.5f * x * (1.0f + erff(x * 0.70710678118654752f));
}
__device__ __forceinline__ uint32_t s2u(const void* p) {
    uint32_t a;
    asm("{ .reg .u64 t; cvta.to.shared.u64 t, %1; cvt.u32.u64 %0, t; }" : "=r"(a) : "l"(p));
    return a;
}

// ---------------- prep 1: im2col + fp16 convert (16 elems/thread) ----------------
__global__ __launch_bounds__(256) void im2col_prep(const float* __restrict__ img) {
    int t = blockIdx.x * 256 + threadIdx.x;       // M*K/16 threads
    int e = t << 4;
    int m = e / K_TOTAL;
    int k = e - m * K_TOTAL;
    int pi = k / 48, rem = k - pi * 48;           // 16-groups never cross 48-boundary
    int b = m / 196, np = m - b * 196;
    int ph = np / 14, pw = np - ph * 14;
    const float* src =
        img + (size_t)(((b * 224 + ph * 16 + pi) * 224 + pw * 16) * 3 + rem);
    float4 v0 = *(const float4*)src;
    float4 v1 = *(const float4*)(src + 4);
    float4 v2 = *(const float4*)(src + 8);
    float4 v3 = *(const float4*)(src + 12);

    union { __half h[16]; uint4 u[2]; } o;
    o.h[0]  = __float2half_rn(v0.x); o.h[1]  = __float2half_rn(v0.y);
    o.h[2]  = __float2half_rn(v0.z); o.h[3]  = __float2half_rn(v0.w);
    o.h[4]  = __float2half_rn(v1.x); o.h[5]  = __float2half_rn(v1.y);
    o.h[6]  = __float2half_rn(v1.z); o.h[7]  = __float2half_rn(v1.w);
    o.h[8]  = __float2half_rn(v2.x); o.h[9]  = __float2half_rn(v2.y);
    o.h[10] = __float2half_rn(v2.z); o.h[11] = __float2half_rn(v2.w);
    o.h[12] = __float2half_rn(v3.x); o.h[13] = __float2half_rn(v3.y);
    o.h[14] = __float2half_rn(v3.z); o.h[15] = __float2half_rn(v3.w);
    uint4* dst = (uint4*)(g_A16 + (size_t)m * K_TOTAL + k);
    dst[0] = o.u[0];
    dst[1] = o.u[1];
}

// ---------------- prep 2: W [K,N] -> [N,K] fp16 ----------------
__global__ __launch_bounds__(1024) void wprep(const float* __restrict__ W) {
    __shared__ float ts[32][33];
    int k0 = blockIdx.y * 32, n0 = blockIdx.x * 32;
    ts[threadIdx.y][threadIdx.x] =
        W[(size_t)(k0 + threadIdx.y) * N_TOTAL + n0 + threadIdx.x];
    __syncthreads();
    g_B16[(size_t)(n0 + threadIdx.y) * K_TOTAL + (k0 + threadIdx.x)] =
        __float2half_rn(ts[threadIdx.x][threadIdx.y]);
}

// ---------------- smem helpers ----------------
// tile row = 64 fp16 = 128 B = 8 x 16B chunks; swizzle: chunk ^= (row & 7)
__device__ __forceinline__ uint32_t sw_off(int row, int chunk) {
    return (uint32_t)(row * 128 + (((chunk) ^ (row & 7)) << 4));
}
__device__ __forceinline__ void cpa16(uint32_t dst, const void* src) {
    asm volatile("cp.async.cg.shared.global [%0], [%1], 16;" ::"r"(dst), "l"(src)
                 : "memory");
}

__device__ __forceinline__ void load_stage(uint32_t st, int kt, int mBlock, int nBlock,
                                           int tid) {
    const size_t kOff = (size_t)kt * BK;
    const __half* gA = g_A16 + (size_t)mBlock * K_TOTAL + kOff;
    const __half* gB = g_B16 + (size_t)nBlock * K_TOTAL + kOff;
#pragma unroll
    for (int i = 0; i < 8; ++i) {                 // A: 1024 chunks / 128 threads
        int cid = i * 128 + tid;
        int row = cid >> 3, ch = cid & 7;
        cpa16(st + sw_off(row, ch), gA + (size_t)row * K_TOTAL + ch * 8);
    }
#pragma unroll
    for (int i = 0; i < 8; ++i) {                 // B
        int cid = i * 128 + tid;
        int row = cid >> 3, ch = cid & 7;
        cpa16(st + TILE_B + sw_off(row, ch), gB + (size_t)row * K_TOTAL + ch * 8);
    }
}

#define LDSM_X4(r0, r1, r2, r3, addr)                                            \
    asm volatile("ldmatrix.sync.aligned.m8n8.x4.shared.b16 {%0,%1,%2,%3}, [%4];" \
                 : "=r"(r0), "=r"(r1), "=r"(r2), "=r"(r3) : "r"(addr))

#define MMA16816(c, a0, a1, a2, a3, b0, b1)                                     \
    asm volatile("mma.sync.aligned.m16n8k16.row.col.f32.f16.f16.f32 "           \
                 "{%0,%1,%2,%3}, {%4,%5,%6,%7}, {%8,%9}, {%0,%1,%2,%3};"        \
                 : "+f"((c)[0]), "+f"((c)[1]), "+f"((c)[2]), "+f"((c)[3])       \
                 : "r"(a0), "r"(a1), "r"(a2), "r"(a3), "r"(b0), "r"(b1))

#define CP_WAIT(n) asm volatile("cp.async.wait_group %0;" ::"n"(n) : "memory")
#define CP_COMMIT() asm volatile("cp.async.commit_group;" ::: "memory")

// ---------------- main GEMM ----------------
__global__ __launch_bounds__(NTH, 2) void patch_gemm(const float* __restrict__ bias,
                                                     float* __restrict__ out) {
    extern __shared__ char dyn[];
    __shared__ float bias_s[BN];

    const int tid = threadIdx.x;
    const int wid = tid >> 5, lane = tid & 31;
    const int wm = wid & 1;          // 2 warps in M: 64 rows each
    const int wn = wid >> 1;         // 2 warps in N: 64 cols each
    const int nBlock = blockIdx.x * BN;
    const int mBlock = blockIdx.y * BM;

    const uint32_t sbase = (s2u(dyn) + 1023u) & ~1023u;

    if (tid < BN) bias_s[tid] = bias[nBlock + tid];

    // ldmatrix per-lane addressing
    const int lr = (lane & 7) + ((lane >> 3) & 1) * 8;  // row-in-16-block, 0..15
    const int lco = lane >> 4;                          // 0/1: +16B chunk

    float acc[4][8][4];
#pragma unroll
    for (int mi = 0; mi < 4; ++mi)
#pragma unroll
        for (int nj = 0; nj < 8; ++nj)
#pragma unroll
            for (int r = 0; r < 4; ++r) acc[mi][nj][r] = 0.0f;

    // prologue: stages 0,1
    load_stage(sbase + 0 * STAGE_B, 0, mBlock, nBlock, tid);
    CP_COMMIT();
    load_stage(sbase + 1 * STAGE_B, 1, mBlock, nBlock, tid);
    CP_COMMIT();

#pragma unroll 1
    for (int kt = 0; kt < KTILES; ++kt) {
        if (kt + 1 < KTILES) CP_WAIT(1);
        else                 CP_WAIT(0);
        __syncthreads();

        const uint32_t aS = sbase + (kt % NSTAGE) * STAGE_B;
        const uint32_t bS = aS + TILE_B;

#pragma unroll
        for (int ks = 0; ks < 4; ++ks) {
            const int c0 = 2 * ks + lco;
            uint32_t a[4][4];
#pragma unroll
            for (int mi = 0; mi < 4; ++mi) {
                int r = wm * 64 + mi * 16 + lr;
                LDSM_X4(a[mi][0], a[mi][1], a[mi][2], a[mi][3], aS + sw_off(r, c0));
            }
            uint32_t b[4][4];
#pragma unroll
            for (int g = 0; g < 4; ++g) {
                int r = wn * 64 + g * 16 + lr;
                LDSM_X4(b[g][0], b[g][1], b[g][2], b[g][3], bS + sw_off(r, c0));
            }
#pragma unroll
            for (int mi = 0; mi < 4; ++mi)
#pragma unroll
                for (int g = 0; g < 4; ++g) {
                    MMA16816(acc[mi][2 * g], a[mi][0], a[mi][1], a[mi][2], a[mi][3],
                             b[g][0], b[g][2]);
                    MMA16816(acc[mi][2 * g + 1], a[mi][0], a[mi][1], a[mi][2],
                             a[mi][3], b[g][1], b[g][3]);
                }
        }

        if (kt + 2 < KTILES) {
            load_stage(sbase + ((kt + 2) % NSTAGE) * STAGE_B, kt + 2, mBlock, nBlock,
                       tid);
            CP_COMMIT();
        }
    }

    // ---------------- epilogue: bias + exact GELU, float2 stores ----------------
    const int tig = lane & 3, gid = lane >> 2;
#pragma unroll
    for (int mi = 0; mi < 4; ++mi) {
        const int row0 = mBlock + wm * 64 + mi * 16 + gid;
#pragma unroll
        for (int nj = 0; nj < 8; ++nj) {
            const int cloc = wn * 64 + nj * 8 + tig * 2;
            const float b0 = bias_s[cloc], b1 = bias_s[cloc + 1];
            float2 v0, v1;
            v0.x = gelu_exact(acc[mi][nj][0] + b0);
            v0.y = gelu_exact(acc[mi][nj][1] + b1);
            v1.x = gelu_exact(acc[mi][nj][2] + b0);
            v1.y = gelu_exact(acc[mi][nj][3] + b1);
            *(float2*)(out + (size_t)row0 * N_TOTAL + nBlock + cloc) = v0;
            *(float2*)(out + (size_t)(row0 + 8) * N_TOTAL + nBlock + cloc) = v1;
        }
    }
}

// ---------------- launch ----------------
extern "C" void kernel_launch(void* const* d_in, const int* in_sizes, int n_in,
                              void* d_out, int out_size) {
    const float* img = (const float*)d_in[0];   // [64,224,224,3]
    const float* Wp = (const float*)d_in[1];    // [768,768]
    const float* bias = (const float*)d_in[2];  // [768]
    float* out = (float*)d_out;                 // [64,196,768]

    cudaFuncSetAttribute(patch_gemm, cudaFuncAttributeMaxDynamicSharedMemorySize,
                         SMEM_DYN);

    im2col_prep<<<M_TOTAL * K_TOTAL / 16 / 256, 256>>>(img);
    wprep<<<dim3(N_TOTAL / 32, K_TOTAL / 32), dim3(32, 32)>>>(Wp);
    patch_gemm<<<dim3(N_TOTAL / BN, M_TOTAL / BM), NTH, SMEM_DYN>>>(bias, out);
}

// round 17
// speedup vs baseline: 1.0925x; 1.0925x over previous
#include <cuda_runtime.h>
#include <cuda_fp16.h>
#include <math.h>
#include <stdint.h>

// PatchEmbedding via single-pass fp16 mma.sync GEMM (sm_103 non-'a': no tcgen05).
// D = GELU( A @ W + b ), M=12544, K=768, N=768, fp32 in/out, fp32 accumulate.
//
// Two launches only:
//  1) prep: fused im2col->fp16 A scratch (32 elems/thread, MLP 8) AND
//     W [K,N] -> [N,K] fp16 transpose (block-partitioned in the same grid).
//  2) patch_gemm: best-known config (CTA 128x128, 8 warps 4Mx2N, warp tile
//     32x64, BK=64, 3-stage cp.async, occ 2, register-double-buffered frags).

#define M_TOTAL 12544
#define K_TOTAL 768
#define N_TOTAL 768
#define BM      128
#define BN      128
#define BK      64              // fp16 per k-tile row chunk (128 B rows)
#define KTILES  12              // 768 / 64
#define TILE_B  16384           // 128 rows * 128 B
#define STAGE_B (2 * TILE_B)    // A tile + B tile
#define NSTAGE  3
#define SMEM_DYN (NSTAGE * STAGE_B + 1024)

// prep grid split
#define IMBLKS  1176            // M*K/32/256
#define WBLKS   576             // 24*24 tiles of 32x32
#define PREPBLKS (IMBLKS + WBLKS)

// ---------------- device scratch ----------------
__device__ __half g_A16[(size_t)M_TOTAL * K_TOTAL];
__device__ __half g_B16[(size_t)N_TOTAL * K_TOTAL];   // W transposed: [N,K]

__device__ __forceinline__ float gelu_exact(float x) {
    return 0.5f * x * (1.0f + erff(x * 0.70710678118654752f));
}
__device__ __forceinline__ uint32_t s2u(const void* p) {
    uint32_t a;
    asm("{ .reg .u64 t; cvta.to.shared.u64 t, %1; cvt.u32.u64 %0, t; }" : "=r"(a) : "l"(p));
    return a;
}

// ---------------- combined prep kernel ----------------
__global__ __launch_bounds__(256) void prep(const float* __restrict__ img,
                                            const float* __restrict__ W) {
    const int bid = blockIdx.x;
    const int tid = threadIdx.x;

    if (bid < IMBLKS) {
        // ---- im2col + fp16 convert, 32 elems/thread (8 LDG.128 in flight) ----
        int t = bid * 256 + tid;
        int m = t / 24;                    // 24 x 32-elem chunks per row
        int k = (t - m * 24) << 5;         // 0,32,...,736
        int b = m / 196, np = m - b * 196;
        int ph = np / 14, pw = np - ph * 14;
        const float* rbase =
            img + (size_t)(((b * 224 + ph * 16) * 224 + pw * 16) * 3);

        float4 v[8];
#pragma unroll
        for (int h = 0; h < 2; ++h) {      // two 16-elem halves (pi may differ)
            int kk = k + 16 * h;
            int pi = kk / 48, rem = kk - pi * 48;
            const float* src = rbase + pi * 672 + rem;
#pragma unroll
            for (int q = 0; q < 4; ++q) v[4 * h + q] = *(const float4*)(src + 4 * q);
        }
        union { __half hh[32]; uint4 u[4]; } o;
#pragma unroll
        for (int q = 0; q < 8; ++q) {
            o.hh[4 * q + 0] = __float2half_rn(v[q].x);
            o.hh[4 * q + 1] = __float2half_rn(v[q].y);
            o.hh[4 * q + 2] = __float2half_rn(v[q].z);
            o.hh[4 * q + 3] = __float2half_rn(v[q].w);
        }
        uint4* dst = (uint4*)(g_A16 + (size_t)m * K_TOTAL + k);
#pragma unroll
        for (int q = 0; q < 4; ++q) dst[q] = o.u[q];
    } else {
        // ---- W [K,N] -> [N,K] fp16 transpose, 32x32 tile per block ----
        __shared__ float ts[32][33];
        const int b2 = bid - IMBLKS;
        const int n0 = (b2 % 24) * 32, k0 = (b2 / 24) * 32;
        {
            int r = tid >> 3, c4 = (tid & 7) * 4;
            float4 v = *(const float4*)(W + (size_t)(k0 + r) * N_TOTAL + n0 + c4);
            ts[r][c4 + 0] = v.x;
            ts[r][c4 + 1] = v.y;
            ts[r][c4 + 2] = v.z;
            ts[r][c4 + 3] = v.w;
        }
        __syncthreads();
        {
            int nr = tid >> 3, c0 = (tid & 7) * 4;
            union { __half hh[4]; uint2 u; } o;
#pragma unroll
            for (int q = 0; q < 4; ++q)
                o.hh[q] = __float2half_rn(ts[c0 + q][nr]);
            *(uint2*)(g_B16 + (size_t)(n0 + nr) * K_TOTAL + k0 + c0) = o.u;
        }
    }
}

// ---------------- smem helpers ----------------
// tile row = 64 fp16 = 128 B = 8 x 16B chunks; swizzle: chunk ^= (row & 7)
__device__ __forceinline__ uint32_t sw_off(int row, int chunk) {
    return (uint32_t)(row * 128 + (((chunk) ^ (row & 7)) << 4));
}
__device__ __forceinline__ void cpa16(uint32_t dst, const void* src) {
    asm volatile("cp.async.cg.shared.global [%0], [%1], 16;" ::"r"(dst), "l"(src)
                 : "memory");
}

__device__ __forceinline__ void load_stage(uint32_t st, int kt, int mBlock, int nBlock,
                                           int tid) {
    const size_t kOff = (size_t)kt * BK;
    const __half* gA = g_A16 + (size_t)mBlock * K_TOTAL + kOff;
    const __half* gB = g_B16 + (size_t)nBlock * K_TOTAL + kOff;
#pragma unroll
    for (int i = 0; i < 4; ++i) {                 // A: 1024 chunks / 256 threads
        int cid = i * 256 + tid;
        int row = cid >> 3, ch = cid & 7;
        cpa16(st + sw_off(row, ch), gA + (size_t)row * K_TOTAL + ch * 8);
    }
#pragma unroll
    for (int i = 0; i < 4; ++i) {                 // B
        int cid = i * 256 + tid;
        int row = cid >> 3, ch = cid & 7;
        cpa16(st + TILE_B + sw_off(row, ch), gB + (size_t)row * K_TOTAL + ch * 8);
    }
}

#define LDSM_X4(r0, r1, r2, r3, addr)                                            \
    asm volatile("ldmatrix.sync.aligned.m8n8.x4.shared.b16 {%0,%1,%2,%3}, [%4];" \
                 : "=r"(r0), "=r"(r1), "=r"(r2), "=r"(r3) : "r"(addr))

#define MMA16816(c, a0, a1, a2, a3, b0, b1)                                     \
    asm volatile("mma.sync.aligned.m16n8k16.row.col.f32.f16.f16.f32 "           \
                 "{%0,%1,%2,%3}, {%4,%5,%6,%7}, {%8,%9}, {%0,%1,%2,%3};"        \
                 : "+f"((c)[0]), "+f"((c)[1]), "+f"((c)[2]), "+f"((c)[3])       \
                 : "r"(a0), "r"(a1), "r"(a2), "r"(a3), "r"(b0), "r"(b1))

#define CP_WAIT(n) asm volatile("cp.async.wait_group %0;" ::"n"(n) : "memory")
#define CP_COMMIT() asm volatile("cp.async.commit_group;" ::: "memory")

// ---------------- main GEMM ----------------
__global__ __launch_bounds__(256, 2) void patch_gemm(const float* __restrict__ bias,
                                                     float* __restrict__ out) {
    extern __shared__ char dyn[];
    __shared__ float bias_s[BN];

    const int tid = threadIdx.x;
    const int wid = tid >> 5, lane = tid & 31;
    const int wm = wid & 3;          // 4 warps in M: 32 rows each
    const int wn = wid >> 2;         // 2 warps in N: 64 cols each
    const int nBlock = blockIdx.x * BN;
    const int mBlock = blockIdx.y * BM;

    const uint32_t sbase = (s2u(dyn) + 1023u) & ~1023u;

    if (tid < BN) bias_s[tid] = bias[nBlock + tid];

    // ldmatrix per-lane addressing
    const int lr = (lane & 7) + ((lane >> 3) & 1) * 8;  // row-in-16-block, 0..15
    const int lco = lane >> 4;                          // 0/1: +16B chunk

    float acc[2][8][4];
#pragma unroll
    for (int mi = 0; mi < 2; ++mi)
#pragma unroll
        for (int nj = 0; nj < 8; ++nj)
#pragma unroll
            for (int r = 0; r < 4; ++r) acc[mi][nj][r] = 0.0f;

    // prologue: stages 0,1
    load_stage(sbase + 0 * STAGE_B, 0, mBlock, nBlock, tid);
    CP_COMMIT();
    load_stage(sbase + 1 * STAGE_B, 1, mBlock, nBlock, tid);
    CP_COMMIT();

#pragma unroll 1
    for (int kt = 0; kt < KTILES; ++kt) {
        if (kt + 1 < KTILES) CP_WAIT(1);
        else                 CP_WAIT(0);
        __syncthreads();

        const uint32_t aS = sbase + (kt % NSTAGE) * STAGE_B;
        const uint32_t bS = aS + TILE_B;

        // register double buffers for fragments
        uint32_t a[2][2][4], b[2][4][4];

        // load ks=0 into buffer 0
        {
            const int c0 = lco;
#pragma unroll
            for (int mi = 0; mi < 2; ++mi) {
                int r = wm * 32 + mi * 16 + lr;
                LDSM_X4(a[0][mi][0], a[0][mi][1], a[0][mi][2], a[0][mi][3],
                        aS + sw_off(r, c0));
            }
#pragma unroll
            for (int g = 0; g < 4; ++g) {
                int r = wn * 64 + g * 16 + lr;
                LDSM_X4(b[0][g][0], b[0][g][1], b[0][g][2], b[0][g][3],
                        bS + sw_off(r, c0));
            }
        }

#pragma unroll
        for (int ks = 0; ks < 4; ++ks) {
            const int cur = ks & 1, nxt = cur ^ 1;
            if (ks < 3) {
                const int c1 = 2 * (ks + 1) + lco;
#pragma unroll
                for (int mi = 0; mi < 2; ++mi) {
                    int r = wm * 32 + mi * 16 + lr;
                    LDSM_X4(a[nxt][mi][0], a[nxt][mi][1], a[nxt][mi][2],
                            a[nxt][mi][3], aS + sw_off(r, c1));
                }
#pragma unroll
                for (int g = 0; g < 4; ++g) {
                    int r = wn * 64 + g * 16 + lr;
                    LDSM_X4(b[nxt][g][0], b[nxt][g][1], b[nxt][g][2],
                            b[nxt][g][3], bS + sw_off(r, c1));
                }
            }
#pragma unroll
            for (int mi = 0; mi < 2; ++mi)
#pragma unroll
                for (int g = 0; g < 4; ++g) {
                    MMA16816(acc[mi][2 * g], a[cur][mi][0], a[cur][mi][1],
                             a[cur][mi][2], a[cur][mi][3], b[cur][g][0],
                             b[cur][g][2]);
                    MMA16816(acc[mi][2 * g + 1], a[cur][mi][0], a[cur][mi][1],
                             a[cur][mi][2], a[cur][mi][3], b[cur][g][1],
                             b[cur][g][3]);
                }
        }

        if (kt + 2 < KTILES) {
            load_stage(sbase + ((kt + 2) % NSTAGE) * STAGE_B, kt + 2, mBlock, nBlock,
                       tid);
            CP_COMMIT();
        }
    }

    // ---------------- epilogue: bias + exact GELU, float2 stores ----------------
    const int tig = lane & 3, gid = lane >> 2;
#pragma unroll
    for (int mi = 0; mi < 2; ++mi) {
        const int row0 = mBlock + wm * 32 + mi * 16 + gid;
#pragma unroll
        for (int nj = 0; nj < 8; ++nj) {
            const int cloc = wn * 64 + nj * 8 + tig * 2;
            const float b0 = bias_s[cloc], b1 = bias_s[cloc + 1];
            float2 v0, v1;
            v0.x = gelu_exact(acc[mi][nj][0] + b0);
            v0.y = gelu_exact(acc[mi][nj][1] + b1);
            v1.x = gelu_exact(acc[mi][nj][2] + b0);
            v1.y = gelu_exact(acc[mi][nj][3] + b1);
            *(float2*)(out + (size_t)row0 * N_TOTAL + nBlock + cloc) = v0;
            *(float2*)(out + (size_t)(row0 + 8) * N_TOTAL + nBlock + cloc) = v1;
        }
    }
}

// ---------------- launch ----------------
extern "C" void kernel_launch(void* const* d_in, const int* in_sizes, int n_in,
                              void* d_out, int out_size) {
    const float* img = (const float*)d_in[0];   // [64,224,224,3]
    const float* Wp = (const float*)d_in[1];    // [768,768]
    const float* bias = (const float*)d_in[2];  // [768]
    float* out = (float*)d_out;                 // [64,196,768]

    cudaFuncSetAttribute(patch_gemm, cudaFuncAttributeMaxDynamicSharedMemorySize,
                         SMEM_DYN);

    prep<<<PREPBLKS, 256>>>(img, Wp);
    patch_gemm<<<dim3(N_TOTAL / BN, M_TOTAL / BM), 256, SMEM_DYN>>>(bias, out);
}